// round 14
// baseline (speedup 1.0000x reference)
#include <cuda_runtime.h>

#define N_NODES 10000
#define KK1 10
#define KK2 25
#define DIM 64
#define OUTD 128
#define NGRAPH 64
#define NSLOT 4
#define GRID 148

typedef unsigned long long ull;

__device__ float g_Seg[NGRAPH * OUTD];

__device__ __forceinline__ void ffma2(ull& acc, ull a, ull b) {
    asm("fma.rn.f32x2 %0, %1, %2, %0;" : "+l"(acc) : "l"(a), "l"(b));
}
__device__ __forceinline__ float f2sum(ull v) {
    return __uint_as_float((unsigned)v) + __uint_as_float((unsigned)(v >> 32));
}
__device__ __forceinline__ unsigned smem_u32(const void* p) {
    unsigned a;
    asm("{ .reg .u64 t; cvta.to.shared.u64 t, %1; cvt.u32.u64 %0, t; }"
        : "=r"(a) : "l"(p));
    return a;
}
__device__ __forceinline__ void mbar_init(unsigned addr, unsigned cnt) {
    asm volatile("mbarrier.init.shared.b64 [%0], %1;" :: "r"(addr), "r"(cnt) : "memory");
}
__device__ __forceinline__ void mbar_arrive(unsigned addr) {
    asm volatile("mbarrier.arrive.release.cta.shared::cta.b64 _, [%0];" :: "r"(addr) : "memory");
}
__device__ __forceinline__ void mbar_wait(unsigned addr, int phase) {
    asm volatile(
        "{\n\t.reg .pred P;\n\t"
        "WL_%=:\n\t"
        "mbarrier.try_wait.parity.acquire.cta.shared::cta.b64 P, [%0], %1, 0x989680;\n\t"
        "@P bra.uni WD_%=;\n\t"
        "bra.uni WL_%=;\n\t"
        "WD_%=:\n\t}"
        :: "r"(addr), "r"(phase) : "memory");
}

#define W0T_LD 132
#define W1T_LD 260
#define XS_NODE 1408
#define XS_PAIR 2816
#define MAXROWS 68

// smem layout (floats):
//   [0:16)    mbarriers (64 B)
//   [16:17424)            XRs: 68 rows x 256
//   [17424:...) overlay:
//     phase 1: w0T (16896) + b0s (128) + ring (NSLOT*2816=11264) = 28288
//     phase 2: w1T (33280) + sgid (68)                            = 33348
#define OFF_XRS 16
#define OFF_LOW (OFF_XRS + MAXROWS * 256)       // 17424
#define SM_FLOATS (OFF_LOW + 33280 + 68)        // 50772 -> 203,088 B

// ---------------------------------------------------------------------------
// kZ: zero segment accumulator (kA epilogue atomicAdds into it).
// ---------------------------------------------------------------------------
extern "C" __global__ void kZ() {
    g_Seg[blockIdx.x * 512 + threadIdx.x] = 0.f;
}

// ---------------------------------------------------------------------------
// Kernel A: R12's proven 384-thread phase 1 (warp-specialized streaming +
// GEMM1, XR rows -> block-local smem), then a block-local GEMM2 epilogue
// using R12-kB's proven no-spill tiling (plain float, 23 rows x 1 col).
// No global sync anywhere.
// ---------------------------------------------------------------------------
extern "C" __global__ void __launch_bounds__(384, 1)
kA(const float* __restrict__ h0, const float* __restrict__ h1,
   const float* __restrict__ h2, const float* __restrict__ w0,
   const float* __restrict__ b0, const float* __restrict__ w1,
   const float* __restrict__ b1, const int* __restrict__ gid)
{
    extern __shared__ float sm[];
    float* XRs = sm + OFF_XRS;

    const int t   = threadIdx.x;
    const int bid = blockIdx.x;
    const unsigned mb = smem_u32(sm);

    // ======================= PHASE 1 (== R12 kA) =======================
    {
        float* w0Ts = sm + OFF_LOW;            // [128 cols][132]
        float* b0s  = w0Ts + 16896;            // 128
        float* ring = b0s + 128;               // NSLOT * 2816

        if (t == 0) {
            #pragma unroll
            for (int s = 0; s < NSLOT; ++s) {
                mbar_init(mb + s * 16, 256);       // full
                mbar_init(mb + s * 16 + 8, 128);   // empty
            }
        }

        for (int i = t; i < 4096; i += 384) {
            const int k  = i >> 5;
            const int cq = i & 31;
            const float4 v = __ldg((const float4*)(w0 + k * 128) + cq);
            w0Ts[(cq * 4 + 0) * W0T_LD + k] = v.x;
            w0Ts[(cq * 4 + 1) * W0T_LD + k] = v.y;
            w0Ts[(cq * 4 + 2) * W0T_LD + k] = v.z;
            w0Ts[(cq * 4 + 3) * W0T_LD + k] = v.w;
        }
        if (t < 128) b0s[t] = b0[t];
        __syncthreads();

        if (t >= 128) {
            // -------- producer --------
            const int p = t - 128;
            int slot = 0, ph = 1;
            for (int np = bid * 2; np < N_NODES; np += GRID * 2) {
                mbar_wait(mb + slot * 16 + 8, ph);
                float* Xb = ring + slot * XS_PAIR;

                #pragma unroll
                for (int pass = 0; pass < 2; ++pass) {
                    const int task = p + pass * 256;
                    if (task < 320) {
                        const int node = task / 160;
                        const int rem  = task - node * 160;
                        const int j    = rem >> 4;
                        const int c4   = rem & 15;
                        const int base = (np + node) * KK1 + j;
                        const float4* q = (const float4*)(h2 + base * (KK2 * DIM)) + c4;
                        float4 s0 = make_float4(0.f, 0.f, 0.f, 0.f);
                        float4 s1 = make_float4(0.f, 0.f, 0.f, 0.f);
                        #pragma unroll
                        for (int k = 0; k < 24; k += 2) {
                            const float4 a = __ldg(q + k * 16);
                            const float4 b = __ldg(q + (k + 1) * 16);
                            s0.x += a.x; s0.y += a.y; s0.z += a.z; s0.w += a.w;
                            s1.x += b.x; s1.y += b.y; s1.z += b.z; s1.w += b.w;
                        }
                        const float4 a = __ldg(q + 24 * 16);
                        s0.x += a.x; s0.y += a.y; s0.z += a.z; s0.w += a.w;
                        float4* xrow = (float4*)(Xb + node * XS_NODE + j * 128);
                        xrow[16 + c4] = make_float4((s0.x + s1.x) * 0.04f,
                                                    (s0.y + s1.y) * 0.04f,
                                                    (s0.z + s1.z) * 0.04f,
                                                    (s0.w + s1.w) * 0.04f);
                        xrow[c4] = __ldg((const float4*)(h1 + base * DIM) + c4);
                    } else if (task < 352) {
                        const int idx = task - 320;
                        const int node = idx >> 4, c4 = idx & 15;
                        ((float4*)(Xb + node * XS_NODE + 10 * 128))[c4] =
                            __ldg((const float4*)(h0 + (np + node) * DIM) + c4);
                    } else if (task < 384) {
                        const int idx = task - 352;
                        const int node = idx >> 4, c4 = idx & 15;
                        const float4* q = (const float4*)(h1 + (np + node) * KK1 * DIM) + c4;
                        float4 s = make_float4(0.f, 0.f, 0.f, 0.f);
                        #pragma unroll
                        for (int j = 0; j < KK1; ++j) {
                            const float4 v = __ldg(q + j * 16);
                            s.x += v.x; s.y += v.y; s.z += v.z; s.w += v.w;
                        }
                        ((float4*)(Xb + node * XS_NODE + 10 * 128))[16 + c4] =
                            make_float4(s.x * 0.1f, s.y * 0.1f, s.z * 0.1f, s.w * 0.1f);
                    }
                }
                mbar_arrive(mb + slot * 16);
                if (++slot == NSLOT) { slot = 0; ph ^= 1; }
            }
        } else {
            // -------- consumer (2 cols/thread); XR rows -> smem --------
            const int node = t >> 6;
            const int col  = t & 63;
            const ulonglong2* wpa = (const ulonglong2*)(w0Ts + col * W0T_LD);
            const ulonglong2* wpb = (const ulonglong2*)(w0Ts + (col + 64) * W0T_LD);
            const float bbA = b0s[col];
            const float bbB = b0s[col + 64];

            int slot = 0, ph = 0, ip = 0;
            for (int np = bid * 2; np < N_NODES; np += GRID * 2) {
                mbar_wait(mb + slot * 16, ph);
                const float* X = ring + slot * XS_PAIR + node * XS_NODE;

                ull accA[11], accB[11];
                #pragma unroll
                for (int r = 0; r < 11; ++r) { accA[r] = 0ull; accB[r] = 0ull; }

                #pragma unroll 2
                for (int kq = 0; kq < 32; ++kq) {
                    const ulonglong2 wa = wpa[kq];
                    const ulonglong2 wb = wpb[kq];
                    #pragma unroll
                    for (int r = 0; r < 11; ++r) {
                        const ulonglong2 x = *(const ulonglong2*)(X + r * 128 + kq * 4);
                        ffma2(accA[r], x.x, wa.x);
                        ffma2(accA[r], x.y, wa.y);
                        ffma2(accB[r], x.x, wb.x);
                        ffma2(accB[r], x.y, wb.y);
                    }
                }

                float ymA = 0.f, ymB = 0.f;
                #pragma unroll
                for (int r = 0; r < KK1; ++r) {
                    ymA += fmaxf(f2sum(accA[r]) + bbA, 0.f);
                    ymB += fmaxf(f2sum(accB[r]) + bbB, 0.f);
                }
                const float a01A = fmaxf(f2sum(accA[10]) + bbA, 0.f);
                const float a01B = fmaxf(f2sum(accB[10]) + bbB, 0.f);

                float* xr = XRs + (2 * ip + node) * 256;
                xr[col]            = a01A;
                xr[col + 64]       = a01B;
                xr[128 + col]      = ymA * 0.1f;
                xr[128 + col + 64] = ymB * 0.1f;

                mbar_arrive(mb + slot * 16 + 8);
                if (++slot == NSLOT) { slot = 0; ph ^= 1; }
                ++ip;
            }
        }
    }

    __syncthreads();   // phase 1 complete block-locally; w0T/ring now dead

    // ====== PHASE 2 (block-local epilogue): relu(XR@w1+b1) -> seg atomics ======
    {
        float* w1Ts = sm + OFF_LOW;                 // [128][260]
        int*   sgid = (int*)(sm + OFF_LOW + 33280); // 68 ints

        const int npairs = (N_NODES - bid * 2 + GRID * 2 - 1) / (GRID * 2);
        const int nrows  = 2 * npairs;              // 66 or 68

        // Restage w1 transposed (R12-proven: coalesced LDG, conflict-free STS.128)
        for (int i = t; i < 8192; i += 384) {
            const int c = i & 127, kq = i >> 7;
            float4 v;
            v.x = __ldg(w1 + (kq * 4 + 0) * 128 + c);
            v.y = __ldg(w1 + (kq * 4 + 1) * 128 + c);
            v.z = __ldg(w1 + (kq * 4 + 2) * 128 + c);
            v.w = __ldg(w1 + (kq * 4 + 3) * 128 + c);
            ((float4*)(w1Ts + c * W1T_LD))[kq] = v;
        }
        if (t < nrows)
            sgid[t] = __ldg(gid + bid * 2 + (t >> 1) * (GRID * 2) + (t & 1));
        __syncthreads();

        const int c  = t & 127;                     // output column
        const int rg = t >> 7;                      // row-group 0..2 (23 rows)
        const float bb = __ldg(b1 + c);
        const float4* wp = (const float4*)(w1Ts + c * W1T_LD);

        float acc[23];
        #pragma unroll
        for (int r = 0; r < 23; ++r) acc[r] = 0.f;

        const float* xb = XRs + (rg * 23) * 256;
        #pragma unroll 2
        for (int kq = 0; kq < 64; ++kq) {
            const float4 w = wp[kq];
            #pragma unroll
            for (int r = 0; r < 23; ++r) {
                const float4 x = *(const float4*)(xb + r * 256 + kq * 4);
                float a = acc[r];
                a = fmaf(x.x, w.x, a);
                a = fmaf(x.y, w.y, a);
                a = fmaf(x.z, w.z, a);
                a = fmaf(x.w, w.w, a);
                acc[r] = a;
            }
        }

        // relu + run-length coalesced atomics (adjacent pair rows share gid)
        int curg = (rg * 23 < nrows) ? sgid[rg * 23] : -1;
        float s = 0.f;
        #pragma unroll
        for (int r = 0; r < 23; ++r) {
            const int row = rg * 23 + r;
            if (row < nrows) {
                const float y = fmaxf(acc[r] + bb, 0.f);
                const int g = sgid[row];
                if (g != curg) {
                    if (curg >= 0) atomicAdd(&g_Seg[curg * OUTD + c], s);
                    s = 0.f; curg = g;
                }
                s += y;
            }
        }
        if (curg >= 0) atomicAdd(&g_Seg[curg * OUTD + c], s);
    }
}

// ---------------------------------------------------------------------------
// Kernel C: readout MLP, one block per graph (kernel boundary = global sync).
// ---------------------------------------------------------------------------
extern "C" __global__ void __launch_bounds__(64, 8)
kC(const float* __restrict__ wr1, const float* __restrict__ br1,
   const float* __restrict__ wr2, const float* __restrict__ br2,
   const float* __restrict__ wr3, const float* __restrict__ br3,
   float* __restrict__ out)
{
    __shared__ float r1s[35];
    __shared__ float r2s[35];
    const int g = blockIdx.x, t = threadIdx.x;
    const float SC = 1.0507009873554805f;
    const float AL = 1.6732632423543772f;

    if (t < 35) {
        float acc = br1[t];
        #pragma unroll 4
        for (int k = 0; k < OUTD; ++k)
            acc = fmaf(g_Seg[g * OUTD + k], wr1[k * 35 + t], acc);
        r1s[t] = (acc > 0.f) ? SC * acc : SC * AL * (expf(acc) - 1.f);
    }
    __syncthreads();

    if (t < 35) {
        float acc = br2[t];
        #pragma unroll
        for (int k = 0; k < 35; ++k)
            acc = fmaf(r1s[k], wr2[k * 35 + t], acc);
        r2s[t] = (acc > 0.f) ? SC * acc : SC * AL * (expf(acc) - 1.f);
    }
    __syncthreads();

    if (t == 0) {
        float acc = br3[0];
        #pragma unroll
        for (int k = 0; k < 35; ++k)
            acc = fmaf(r2s[k], wr3[k], acc);
        out[g] = acc;
    }
}

// ---------------------------------------------------------------------------
extern "C" void kernel_launch(void* const* d_in, const int* in_sizes, int n_in,
                              void* d_out, int out_size)
{
    const float* h0  = (const float*)d_in[0];
    const float* h1  = (const float*)d_in[1];
    const float* h2  = (const float*)d_in[2];
    const float* w0  = (const float*)d_in[3];
    const float* b0  = (const float*)d_in[4];
    const float* w1  = (const float*)d_in[5];
    const float* b1  = (const float*)d_in[6];
    const float* wr1 = (const float*)d_in[7];
    const float* br1 = (const float*)d_in[8];
    const float* wr2 = (const float*)d_in[9];
    const float* br2 = (const float*)d_in[10];
    const float* wr3 = (const float*)d_in[11];
    const float* br3 = (const float*)d_in[12];
    const int*   gid = (const int*)d_in[13];

    const int smA = SM_FLOATS * 4;   // 203,088 B
    cudaFuncSetAttribute(kA, cudaFuncAttributeMaxDynamicSharedMemorySize, smA);

    kZ<<<16, 512>>>();
    kA<<<GRID, 384, smA>>>(h0, h1, h2, w0, b0, w1, b1, gid);
    kC<<<NGRAPH, 64>>>(wr1, br1, wr2, br2, wr3, br3, (float*)d_out);
}

// round 15
// speedup vs baseline: 1.2256x; 1.2256x over previous
#include <cuda_runtime.h>

#define N_NODES 10000
#define KK1 10
#define KK2 25
#define DIM 64
#define OUTD 128
#define NGRAPH 64
#define NSLOT 4
#define GRID 148

typedef unsigned long long ull;

__device__ float g_XR[N_NODES * 256];   // per node0: [a01(128) | mean_relu_a12(128)]
__device__ float g_Seg[NGRAPH * OUTD];

__device__ __forceinline__ void ffma2(ull& acc, ull a, ull b) {
    asm("fma.rn.f32x2 %0, %1, %2, %0;" : "+l"(acc) : "l"(a), "l"(b));
}
__device__ __forceinline__ float f2sum(ull v) {
    return __uint_as_float((unsigned)v) + __uint_as_float((unsigned)(v >> 32));
}
__device__ __forceinline__ unsigned smem_u32(const void* p) {
    unsigned a;
    asm("{ .reg .u64 t; cvta.to.shared.u64 t, %1; cvt.u32.u64 %0, t; }"
        : "=r"(a) : "l"(p));
    return a;
}
__device__ __forceinline__ void mbar_init(unsigned addr, unsigned cnt) {
    asm volatile("mbarrier.init.shared.b64 [%0], %1;" :: "r"(addr), "r"(cnt) : "memory");
}
__device__ __forceinline__ void mbar_arrive(unsigned addr) {
    asm volatile("mbarrier.arrive.release.cta.shared::cta.b64 _, [%0];" :: "r"(addr) : "memory");
}
__device__ __forceinline__ void mbar_wait(unsigned addr, int phase) {
    asm volatile(
        "{\n\t.reg .pred P;\n\t"
        "WL_%=:\n\t"
        "mbarrier.try_wait.parity.acquire.cta.shared::cta.b64 P, [%0], %1, 0x989680;\n\t"
        "@P bra.uni WD_%=;\n\t"
        "bra.uni WL_%=;\n\t"
        "WD_%=:\n\t}"
        :: "r"(addr), "r"(phase) : "memory");
}

#define W0T_LD 132
#define W1T_LD 260
#define XS_NODE 1408
#define XS_PAIR 2816

// ---------------------------------------------------------------------------
// Kernel A: EXACT copy of the proven R12 config (142.6us).
// ---------------------------------------------------------------------------
extern "C" __global__ void __launch_bounds__(384, 1)
kA(const float* __restrict__ h0, const float* __restrict__ h1,
   const float* __restrict__ h2, const float* __restrict__ w0,
   const float* __restrict__ b0)
{
    extern __shared__ float sm[];
    float* w0Ts = sm + 8;                  // [128 cols][132]
    float* b0s  = w0Ts + 16896;            // 128
    float* ring = b0s + 128;               // NSLOT * 2816

    const int t = threadIdx.x;
    const unsigned mb = smem_u32(sm);

    if (t == 0) {
        #pragma unroll
        for (int s = 0; s < NSLOT; ++s) {
            mbar_init(mb + s * 16, 256);       // full
            mbar_init(mb + s * 16 + 8, 128);   // empty
        }
    }

    // Zero segment accumulator (kB runs after kA in stream order).
    if (blockIdx.x < 22) {
        const int idx = blockIdx.x * 384 + t;
        if (idx < NGRAPH * OUTD) g_Seg[idx] = 0.f;
    }

    for (int i = t; i < 4096; i += 384) {
        const int k  = i >> 5;
        const int cq = i & 31;
        const float4 v = __ldg((const float4*)(w0 + k * 128) + cq);
        w0Ts[(cq * 4 + 0) * W0T_LD + k] = v.x;
        w0Ts[(cq * 4 + 1) * W0T_LD + k] = v.y;
        w0Ts[(cq * 4 + 2) * W0T_LD + k] = v.z;
        w0Ts[(cq * 4 + 3) * W0T_LD + k] = v.w;
    }
    if (t < 128) b0s[t] = b0[t];
    __syncthreads();

    if (t >= 128) {
        // -------- producer --------
        const int p = t - 128;
        int slot = 0, ph = 1;
        for (int np = blockIdx.x * 2; np < N_NODES; np += GRID * 2) {
            mbar_wait(mb + slot * 16 + 8, ph);
            float* Xb = ring + slot * XS_PAIR;

            #pragma unroll
            for (int pass = 0; pass < 2; ++pass) {
                const int task = p + pass * 256;
                if (task < 320) {
                    const int node = task / 160;
                    const int rem  = task - node * 160;
                    const int j    = rem >> 4;
                    const int c4   = rem & 15;
                    const int base = (np + node) * KK1 + j;
                    const float4* q = (const float4*)(h2 + base * (KK2 * DIM)) + c4;
                    float4 s0 = make_float4(0.f, 0.f, 0.f, 0.f);
                    float4 s1 = make_float4(0.f, 0.f, 0.f, 0.f);
                    #pragma unroll
                    for (int k = 0; k < 24; k += 2) {
                        const float4 a = __ldg(q + k * 16);
                        const float4 b = __ldg(q + (k + 1) * 16);
                        s0.x += a.x; s0.y += a.y; s0.z += a.z; s0.w += a.w;
                        s1.x += b.x; s1.y += b.y; s1.z += b.z; s1.w += b.w;
                    }
                    const float4 a = __ldg(q + 24 * 16);
                    s0.x += a.x; s0.y += a.y; s0.z += a.z; s0.w += a.w;
                    float4* xrow = (float4*)(Xb + node * XS_NODE + j * 128);
                    xrow[16 + c4] = make_float4((s0.x + s1.x) * 0.04f,
                                                (s0.y + s1.y) * 0.04f,
                                                (s0.z + s1.z) * 0.04f,
                                                (s0.w + s1.w) * 0.04f);
                    xrow[c4] = __ldg((const float4*)(h1 + base * DIM) + c4);
                } else if (task < 352) {
                    const int idx = task - 320;
                    const int node = idx >> 4, c4 = idx & 15;
                    ((float4*)(Xb + node * XS_NODE + 10 * 128))[c4] =
                        __ldg((const float4*)(h0 + (np + node) * DIM) + c4);
                } else if (task < 384) {
                    const int idx = task - 352;
                    const int node = idx >> 4, c4 = idx & 15;
                    const float4* q = (const float4*)(h1 + (np + node) * KK1 * DIM) + c4;
                    float4 s = make_float4(0.f, 0.f, 0.f, 0.f);
                    #pragma unroll
                    for (int j = 0; j < KK1; ++j) {
                        const float4 v = __ldg(q + j * 16);
                        s.x += v.x; s.y += v.y; s.z += v.z; s.w += v.w;
                    }
                    ((float4*)(Xb + node * XS_NODE + 10 * 128))[16 + c4] =
                        make_float4(s.x * 0.1f, s.y * 0.1f, s.z * 0.1f, s.w * 0.1f);
                }
            }
            mbar_arrive(mb + slot * 16);
            if (++slot == NSLOT) { slot = 0; ph ^= 1; }
        }
    } else {
        // -------- consumer (2 cols/thread) --------
        const int node = t >> 6;
        const int col  = t & 63;
        const ulonglong2* wpa = (const ulonglong2*)(w0Ts + col * W0T_LD);
        const ulonglong2* wpb = (const ulonglong2*)(w0Ts + (col + 64) * W0T_LD);
        const float bbA = b0s[col];
        const float bbB = b0s[col + 64];

        int slot = 0, ph = 0;
        for (int np = blockIdx.x * 2; np < N_NODES; np += GRID * 2) {
            mbar_wait(mb + slot * 16, ph);
            const float* X = ring + slot * XS_PAIR + node * XS_NODE;

            ull accA[11], accB[11];
            #pragma unroll
            for (int r = 0; r < 11; ++r) { accA[r] = 0ull; accB[r] = 0ull; }

            #pragma unroll 2
            for (int kq = 0; kq < 32; ++kq) {
                const ulonglong2 wa = wpa[kq];
                const ulonglong2 wb = wpb[kq];
                #pragma unroll
                for (int r = 0; r < 11; ++r) {
                    const ulonglong2 x = *(const ulonglong2*)(X + r * 128 + kq * 4);
                    ffma2(accA[r], x.x, wa.x);
                    ffma2(accA[r], x.y, wa.y);
                    ffma2(accB[r], x.x, wb.x);
                    ffma2(accB[r], x.y, wb.y);
                }
            }

            float ymA = 0.f, ymB = 0.f;
            #pragma unroll
            for (int r = 0; r < KK1; ++r) {
                ymA += fmaxf(f2sum(accA[r]) + bbA, 0.f);
                ymB += fmaxf(f2sum(accB[r]) + bbB, 0.f);
            }
            const float a01A = fmaxf(f2sum(accA[10]) + bbA, 0.f);
            const float a01B = fmaxf(f2sum(accB[10]) + bbB, 0.f);

            float* xr = g_XR + (np + node) * 256;
            xr[col]            = a01A;
            xr[col + 64]       = a01B;
            xr[128 + col]      = ymA * 0.1f;
            xr[128 + col + 64] = ymB * 0.1f;

            mbar_arrive(mb + slot * 16 + 8);
            if (++slot == NSLOT) { slot = 0; ph ^= 1; }
        }
    }
}

// ---------------------------------------------------------------------------
// Kernel B (v5): R12's proven structure (68 contiguous rows/block, 512 thr,
// 17 rows x 1 col thread tile, no spill) with the inner loop FFMA2-ized:
// halves FMA issue count; crossbar unchanged (1 weight LDS.128 + 17
// broadcasts per kq per warp).
// ---------------------------------------------------------------------------
#define KB_ROWS 68
extern "C" __global__ void __launch_bounds__(512, 1)
kB(const float* __restrict__ w1, const float* __restrict__ b1,
   const int* __restrict__ gid)
{
    extern __shared__ float sm[];
    float* w1Ts = sm;                        // [128][260] = 33280 floats
    float* xs   = sm + 33280;                // 68 rows x 256 = 17408 floats
    int*   sgid = (int*)(sm + 33280 + 17408);

    const int t  = threadIdx.x;
    const int r0 = blockIdx.x * KB_ROWS;
    const int nrows = min(KB_ROWS, max(0, N_NODES - r0));

    // Stage w1 transposed: coalesced scalar LDG x4, conflict-free STS.128.
    for (int i = t; i < 8192; i += 512) {
        const int c = i & 127, kq = i >> 7;
        float4 v;
        v.x = __ldg(w1 + (kq * 4 + 0) * 128 + c);
        v.y = __ldg(w1 + (kq * 4 + 1) * 128 + c);
        v.z = __ldg(w1 + (kq * 4 + 2) * 128 + c);
        v.w = __ldg(w1 + (kq * 4 + 3) * 128 + c);
        ((float4*)(w1Ts + c * W1T_LD))[kq] = v;
    }
    // Stage this block's 68 XR rows (zero-pad beyond nrows).
    for (int i = t; i < KB_ROWS * 64; i += 512) {
        const int row = i >> 6, q = i & 63;
        ((float4*)(xs + row * 256))[q] = (row < nrows)
            ? __ldg((const float4*)(g_XR + (r0 + row) * 256) + q)
            : make_float4(0.f, 0.f, 0.f, 0.f);
    }
    if (t < KB_ROWS) sgid[t] = (t < nrows) ? __ldg(gid + r0 + t) : -1;
    __syncthreads();

    if (nrows == 0) return;

    const int c  = t & 127;                  // output column
    const int rg = t >> 7;                   // row-group 0..3 (17 rows each)
    const float bb = __ldg(b1 + c);
    const ulonglong2* wp = (const ulonglong2*)(w1Ts + c * W1T_LD);

    ull acc[17];
    #pragma unroll
    for (int r = 0; r < 17; ++r) acc[r] = 0ull;

    const float* xb = xs + (rg * 17) * 256;
    #pragma unroll 2
    for (int kq = 0; kq < 64; ++kq) {
        const ulonglong2 w = wp[kq];
        #pragma unroll
        for (int r = 0; r < 17; ++r) {
            const ulonglong2 x = *(const ulonglong2*)(xb + r * 256 + kq * 4);
            ffma2(acc[r], x.x, w.x);
            ffma2(acc[r], x.y, w.y);
        }
    }

    // relu + run-length coalesced atomics (gids sorted; pad rows gid=-1)
    int curg = sgid[rg * 17];
    float s = 0.f;
    #pragma unroll
    for (int r = 0; r < 17; ++r) {
        const int row = rg * 17 + r;
        if (row < nrows) {
            const float y = fmaxf(f2sum(acc[r]) + bb, 0.f);
            const int g = sgid[row];
            if (g != curg) {
                if (curg >= 0) atomicAdd(&g_Seg[curg * OUTD + c], s);
                s = 0.f; curg = g;
            }
            s += y;
        }
    }
    if (curg >= 0) atomicAdd(&g_Seg[curg * OUTD + c], s);
}

// ---------------------------------------------------------------------------
// Kernel C: readout MLP, one block per graph.
// ---------------------------------------------------------------------------
extern "C" __global__ void __launch_bounds__(64, 8)
kC(const float* __restrict__ wr1, const float* __restrict__ br1,
   const float* __restrict__ wr2, const float* __restrict__ br2,
   const float* __restrict__ wr3, const float* __restrict__ br3,
   float* __restrict__ out)
{
    __shared__ float r1s[35];
    __shared__ float r2s[35];
    const int g = blockIdx.x, t = threadIdx.x;
    const float SC = 1.0507009873554805f;
    const float AL = 1.6732632423543772f;

    if (t < 35) {
        float acc = br1[t];
        #pragma unroll 4
        for (int k = 0; k < OUTD; ++k)
            acc = fmaf(g_Seg[g * OUTD + k], wr1[k * 35 + t], acc);
        r1s[t] = (acc > 0.f) ? SC * acc : SC * AL * (expf(acc) - 1.f);
    }
    __syncthreads();

    if (t < 35) {
        float acc = br2[t];
        #pragma unroll
        for (int k = 0; k < 35; ++k)
            acc = fmaf(r1s[k], wr2[k * 35 + t], acc);
        r2s[t] = (acc > 0.f) ? SC * acc : SC * AL * (expf(acc) - 1.f);
    }
    __syncthreads();

    if (t == 0) {
        float acc = br3[0];
        #pragma unroll
        for (int k = 0; k < 35; ++k)
            acc = fmaf(r2s[k], wr3[k], acc);
        out[g] = acc;
    }
}

// ---------------------------------------------------------------------------
extern "C" void kernel_launch(void* const* d_in, const int* in_sizes, int n_in,
                              void* d_out, int out_size)
{
    const float* h0  = (const float*)d_in[0];
    const float* h1  = (const float*)d_in[1];
    const float* h2  = (const float*)d_in[2];
    const float* w0  = (const float*)d_in[3];
    const float* b0  = (const float*)d_in[4];
    const float* w1  = (const float*)d_in[5];
    const float* b1  = (const float*)d_in[6];
    const float* wr1 = (const float*)d_in[7];
    const float* br1 = (const float*)d_in[8];
    const float* wr2 = (const float*)d_in[9];
    const float* br2 = (const float*)d_in[10];
    const float* wr3 = (const float*)d_in[11];
    const float* br3 = (const float*)d_in[12];
    const int*   gid = (const int*)d_in[13];

    const int smA = (8 + 16896 + 128 + NSLOT * XS_PAIR) * 4;    // 113,184 B
    const int smB = (33280 + 17408 + 68) * 4;                   // 203,024 B
    cudaFuncSetAttribute(kA, cudaFuncAttributeMaxDynamicSharedMemorySize, smA);
    cudaFuncSetAttribute(kB, cudaFuncAttributeMaxDynamicSharedMemorySize, smB);

    kA<<<GRID, 384, smA>>>(h0, h1, h2, w0, b0);
    kB<<<GRID, 512, smB>>>(w1, b1, gid);
    kC<<<NGRAPH, 64>>>(wr1, br1, wr2, br2, wr3, br3, (float*)d_out);
}